// round 2
// baseline (speedup 1.0000x reference)
#include <cuda_runtime.h>
#include <cstdint>

#define BS_ROWS     1024                      // B*S
#define VOCAB       50257
#define DMODEL      768
#define D4          (DMODEL / 4)              // 192 float4 per row
#define TOTAL_ELEMS (BS_ROWS * (long long)VOCAB)   // 51,463,168
#define TOTAL_F4    (TOTAL_ELEMS / 4)              // 12,865,792
#define FULL        0xffffffffu

// ---------------------------------------------------------------------------
// Fused kernel: stream-scan the one-hot tensor; on discovery, the finding
// warp cooperatively writes out[row,:] = val * weight[col,:].
// Hot path per thread-iter: 4x LDG.128 + OR-tree + 1 ballot.
// ---------------------------------------------------------------------------
__device__ __forceinline__ unsigned or16(const uint4& a, const uint4& b,
                                         const uint4& c, const uint4& d)
{
    unsigned m0 = a.x | a.y | a.z;
    unsigned m1 = a.w | b.x | b.y;
    unsigned m2 = b.z | b.w | c.x;
    unsigned m3 = c.y | c.z | c.w;
    unsigned m4 = d.x | d.y | d.z;
    return m0 | m1 | m2 | m3 | m4 | d.w;
}

__device__ __forceinline__ float elem_f(const uint4& a, const uint4& b,
                                        const uint4& c, const uint4& d, int e)
{
    // compile-time selected (called with constant e from unrolled loop)
    const uint4& v = (e < 4) ? a : (e < 8) ? b : (e < 12) ? c : d;
    int k = e & 3;
    unsigned w = (k == 0) ? v.x : (k == 1) ? v.y : (k == 2) ? v.z : v.w;
    return __uint_as_float(w);
}

__device__ __forceinline__ void warp_emit(unsigned em, long long i_src,
                                          long long stride, int lane,
                                          float my_vals_as_shfl_src_a,  // unused marker
                                          const uint4& a, const uint4& b,
                                          const uint4& c, const uint4& d,
                                          int src,
                                          const float4* __restrict__ w4,
                                          float4* __restrict__ out4)
{
    #pragma unroll
    for (int e = 0; e < 16; e++) {
        if (em & (1u << e)) {                       // warp-uniform branch
            float v = __shfl_sync(FULL, elem_f(a, b, c, d, e), src);
            if (v != 0.0f) {
                int u = e >> 2, k = e & 3;
                long long g = (i_src + (long long)u * stride) * 4 + k;
                int row = (int)(g / VOCAB);
                int col = (int)(g - (long long)row * VOCAB);
                const float4* __restrict__ wr = w4 + (long long)col * D4;
                float4* __restrict__       orow = out4 + (long long)row * D4;
                #pragma unroll
                for (int j = 0; j < 6; j++) {       // 32 lanes x 6 = 192 f4
                    float4 t = __ldg(&wr[lane + j * 32]);
                    t.x *= v; t.y *= v; t.z *= v; t.w *= v;
                    orow[lane + j * 32] = t;
                }
            }
        }
    }
}

__global__ void __launch_bounds__(256, 8)
fused_embed_kernel(const uint4* __restrict__ oh4,
                   const float4* __restrict__ w4,
                   float4* __restrict__ out4)
{
    const int lane = threadIdx.x & 31;
    const long long stride = (long long)gridDim.x * blockDim.x;
    long long i = (long long)blockIdx.x * blockDim.x + threadIdx.x;
    // warp-uniform main-loop bound: based on the warp's last lane
    const long long lastlane_off = 31 - lane;

    // ---- main loop: 4-way unrolled, warp-converged ----
    while (i + lastlane_off + 3 * stride < TOTAL_F4) {
        uint4 a = __ldg(&oh4[i]);
        uint4 b = __ldg(&oh4[i + stride]);
        uint4 c = __ldg(&oh4[i + 2 * stride]);
        uint4 d = __ldg(&oh4[i + 3 * stride]);

        unsigned any = or16(a, b, c, d);
        unsigned fmask = __ballot_sync(FULL, any != 0u);
        if (fmask) {                                // rare (~1% of warp-iters)
            // per-lane 16-bit element mask (float compare, excludes -0.0 noise)
            unsigned em_mine = 0;
            #pragma unroll
            for (int e = 0; e < 16; e++)
                em_mine |= (elem_f(a, b, c, d, e) != 0.0f ? 1u : 0u) << e;

            unsigned fm = fmask;
            while (fm) {
                int src = __ffs(fm) - 1; fm &= fm - 1;
                unsigned em = __shfl_sync(FULL, em_mine, src);
                long long i_src = i - lane + src;
                warp_emit(em, i_src, stride, lane, 0.f, a, b, c, d, src, w4, out4);
            }
        }
        i += 4 * stride;
    }

    // ---- tail: per-f4, all lanes stay converged via active ballot ----
    for (;;) {
        bool active = (i < TOTAL_F4);
        unsigned amask = __ballot_sync(FULL, active);
        if (amask == 0) break;
        uint4 a = active ? __ldg(&oh4[i]) : make_uint4(0, 0, 0, 0);
        unsigned any = a.x | a.y | a.z | a.w;
        unsigned fmask = __ballot_sync(FULL, any != 0u);
        if (fmask) {
            unsigned em_mine = 0;
            em_mine |= (__uint_as_float(a.x) != 0.0f ? 1u : 0u) << 0;
            em_mine |= (__uint_as_float(a.y) != 0.0f ? 1u : 0u) << 1;
            em_mine |= (__uint_as_float(a.z) != 0.0f ? 1u : 0u) << 2;
            em_mine |= (__uint_as_float(a.w) != 0.0f ? 1u : 0u) << 3;
            unsigned fm = fmask;
            while (fm) {
                int src = __ffs(fm) - 1; fm &= fm - 1;
                unsigned em = __shfl_sync(FULL, em_mine, src);
                long long i_src = i - lane + src;
                #pragma unroll
                for (int e = 0; e < 4; e++) {
                    if (em & (1u << e)) {
                        float vsel = (e == 0) ? __uint_as_float(a.x)
                                   : (e == 1) ? __uint_as_float(a.y)
                                   : (e == 2) ? __uint_as_float(a.z)
                                              : __uint_as_float(a.w);
                        float v = __shfl_sync(FULL, vsel, src);
                        if (v != 0.0f) {
                            long long g = i_src * 4 + e;
                            int row = (int)(g / VOCAB);
                            int col = (int)(g - (long long)row * VOCAB);
                            const float4* __restrict__ wr = w4 + (long long)col * D4;
                            float4* __restrict__ orow = out4 + (long long)row * D4;
                            #pragma unroll
                            for (int j = 0; j < 6; j++) {
                                float4 t = __ldg(&wr[lane + j * 32]);
                                t.x *= v; t.y *= v; t.z *= v; t.w *= v;
                                orow[lane + j * 32] = t;
                            }
                        }
                    }
                }
            }
        }
        i += stride;
    }
}

// ---------------------------------------------------------------------------
extern "C" void kernel_launch(void* const* d_in, const int* in_sizes, int n_in,
                              void* d_out, int out_size)
{
    const float* one_hot = nullptr;
    const float* weight  = nullptr;
    for (int i = 0; i < n_in; i++) {
        if (in_sizes[i] == (int)TOTAL_ELEMS)     one_hot = (const float*)d_in[i];
        else if (in_sizes[i] == VOCAB * DMODEL)  weight  = (const float*)d_in[i];
    }

    // exactly one wave: 148 SMs x 8 blocks x 256 thr = 2048 thr/SM
    const int threads = 256;
    const int blocks  = 148 * 8;   // 1184
    fused_embed_kernel<<<blocks, threads>>>((const uint4*)one_hot,
                                            (const float4*)weight,
                                            (float4*)d_out);
}